// round 15
// baseline (speedup 1.0000x reference)
#include <cuda_runtime.h>
#include <cuda_bf16.h>
#include <math.h>
#include <stdint.h>

typedef unsigned long long ull;

#define TPB 256
#define GRID1 296      // phase1a: 2 CTAs/SM persistent
#define CHT 128        // samples per chunk (one M=128 MMA tile)
#define ASTR 136       // bf16 row stride for A tiles (272B: 16B-aligned rows)

// ---- gmem padded/fused scalar weight image (float offsets) ----
#define OW5  9520
#define OW6  9568
#define OW7  9888
#define OW89 11688
#define OW10 12408
#define OB1  12528
#define OB2  12588
#define OB3  12620
#define OB4  12632
#define OB5  12636
#define OB6  12648
#define OB7  12680
#define OB89 12740
#define OB10 12752
#define WTOTAL 12764
#define SBASE2 9520                    // phase1b copies [OW5, WTOTAL)
#define SOF2(x) ((x) - SBASE2)
#define SC2_FLOATS (WTOTAL - SBASE2)   // 3244

// ---- bf16 W image for MMA (bf16-element offsets), hi then lo per layer ----
#define WSTR1 128
#define WSTR2 72
#define WSTR3 40
#define WSTR4 24
#define WI_W1H 0                       // 64 x 128
#define WI_W1L 8192
#define WI_W2H 16384                   // 32 x 72
#define WI_W2L 18688
#define WI_W3H 20992                   // 16 x 40
#define WI_W3L 21632
#define WI_W4H 22272                   // 8 x 24
#define WI_W4L 22464
#define WI_TOT 22656                   // 45,312 bytes

// ---- phase1a dynamic smem layout (bytes) ----
#define SB_AH  0                        // A hi: 128 x 136 bf16 = 34,816
#define SB_AL  34816
#define SB_WI  69632                    // W image: 45,312
#define SMEM1A 114944                   // x2 CTAs = 229,888 <= 233,472

struct Params { const float* w[10]; const float* b[10]; };

__device__ float g_stats[152];
__device__ float g_wpad[WTOTAL];
__device__ unsigned short g_wimg[WI_TOT];

// ---------- ptx helpers ----------
__device__ __forceinline__ uint32_t smem_u32(const void* p) {
    uint32_t a;
    asm("{ .reg .u64 t; cvta.to.shared.u64 t, %1; cvt.u32.u64 %0, t; }" : "=r"(a) : "l"(p));
    return a;
}
__device__ __forceinline__ void ldm_x4(uint32_t* r, uint32_t a) {
    asm volatile("ldmatrix.sync.aligned.m8n8.x4.shared.b16 {%0,%1,%2,%3}, [%4];"
        : "=r"(r[0]), "=r"(r[1]), "=r"(r[2]), "=r"(r[3]) : "r"(a));
}
__device__ __forceinline__ void ldm_x2(uint32_t* r, uint32_t a) {
    asm volatile("ldmatrix.sync.aligned.m8n8.x2.shared.b16 {%0,%1}, [%2];"
        : "=r"(r[0]), "=r"(r[1]) : "r"(a));
}
__device__ __forceinline__ void mma_bf16(float* d, const uint32_t* a, uint32_t b0, uint32_t b1) {
    asm volatile(
        "mma.sync.aligned.m16n8k16.row.col.f32.bf16.bf16.f32 "
        "{%0,%1,%2,%3}, {%4,%5,%6,%7}, {%8,%9}, {%0,%1,%2,%3};"
        : "+f"(d[0]), "+f"(d[1]), "+f"(d[2]), "+f"(d[3])
        : "r"(a[0]), "r"(a[1]), "r"(a[2]), "r"(a[3]), "r"(b0), "r"(b1));
}

// ---------- math helpers ----------
__device__ __forceinline__ ull fma2(ull a, ull b, ull c) {
    ull d; asm("fma.rn.f32x2 %0, %1, %2, %3;" : "=l"(d) : "l"(a), "l"(b), "l"(c)); return d;
}
__device__ __forceinline__ ull pack2(float x) {
    ull r; asm("mov.b64 %0, {%1, %1};" : "=l"(r) : "f"(x)); return r;
}
__device__ __forceinline__ void unpack2(float& lo, float& hi, ull v) {
    asm("mov.b64 {%0, %1}, %2;" : "=f"(lo), "=f"(hi) : "l"(v));
}
__device__ __forceinline__ float tanh_fast(float x) {
    float e;
    asm("ex2.approx.f32 %0, %1;" : "=f"(e) : "f"(x * 2.8853900817779268f));
    float r;
    asm("rcp.approx.f32 %0, %1;" : "=f"(r) : "f"(e + 1.0f));
    return fmaf(-2.0f, r, 1.0f);
}
__device__ __forceinline__ uint32_t bf16x2_hi(float a, float b, float& ra, float& rb) {
    __nv_bfloat162 h = __floats2bfloat162_rn(a, b);
    ra = a - __bfloat162float(h.x);
    rb = b - __bfloat162float(h.y);
    return *reinterpret_cast<uint32_t*>(&h);
}
__device__ __forceinline__ uint32_t bf16x2_of(float a, float b) {
    __nv_bfloat162 h = __floats2bfloat162_rn(a, b);
    return *reinterpret_cast<uint32_t*>(&h);
}

// ---------- MMA stage via ldmatrix: d = A(128xK) @ W^T, split-bf16 3-product ----------
template<int NT, int KT>
__device__ __forceinline__ void mma_stage(uint32_t AhU, uint32_t AlU,
                                          uint32_t WhU, uint32_t WlU,
                                          int wstr, float (&d)[NT][4],
                                          int Rb0, int lane) {
#pragma unroll
    for (int nt = 0; nt < NT; nt++)
#pragma unroll
        for (int q = 0; q < 4; q++) d[nt][q] = 0.0f;

    int arow = Rb0 + (lane & 15);
    int acol = (lane >> 4) << 3;
    int wrow = (lane & 7) + ((lane >> 4) & 1) * 8;
    int wcol = ((lane >> 3) & 1) << 3;

#pragma unroll
    for (int kt = 0; kt < KT; kt++) {
        int cb = kt * 16;
        uint32_t aoff = (uint32_t)(arow * ASTR + cb + acol) * 2;
        uint32_t aH[4], aL[4];
        ldm_x4(aH, AhU + aoff);
        ldm_x4(aL, AlU + aoff);
        if constexpr (NT == 1) {
            uint32_t woff = (uint32_t)((lane & 7) * wstr + cb + wcol) * 2;
            uint32_t bH[2], bL[2];
            ldm_x2(bH, WhU + woff);
            ldm_x2(bL, WlU + woff);
            mma_bf16(d[0], aH, bH[0], bH[1]);
            mma_bf16(d[0], aL, bH[0], bH[1]);
            mma_bf16(d[0], aH, bL[0], bL[1]);
        } else {
#pragma unroll
            for (int np = 0; np < NT / 2; np++) {
                int nt0 = np * 2;
                uint32_t woff = (uint32_t)((nt0 * 8 + wrow) * wstr + cb + wcol) * 2;
                uint32_t bH[4], bL[4];
                ldm_x4(bH, WhU + woff);
                ldm_x4(bL, WlU + woff);
                mma_bf16(d[nt0],     aH, bH[0], bH[1]);
                mma_bf16(d[nt0],     aL, bH[0], bH[1]);
                mma_bf16(d[nt0],     aH, bL[0], bL[1]);
                mma_bf16(d[nt0 + 1], aH, bH[2], bH[3]);
                mma_bf16(d[nt0 + 1], aL, bH[2], bH[3]);
                mma_bf16(d[nt0 + 1], aH, bL[2], bL[3]);
            }
        }
    }
}

// ---------- conversion: bias + tanh on frags -> split-bf16 A buffers ----------
template<int NT>
__device__ __forceinline__ void conv_store(float (&d)[NT][4], const float* __restrict__ bias,
                                           char* Ah, char* Al, int row, int tig) {
#pragma unroll
    for (int nt = 0; nt < NT; nt++) {
        int col0 = nt * 8 + tig * 2;
        float bx = bias[col0], by = bias[col0 + 1];
        float v0 = tanh_fast(d[nt][0] + bx);
        float v1 = tanh_fast(d[nt][1] + by);
        float v2 = tanh_fast(d[nt][2] + bx);
        float v3 = tanh_fast(d[nt][3] + by);
        float r0, r1, r2, r3;
        uint32_t h01 = bf16x2_hi(v0, v1, r0, r1);
        uint32_t h23 = bf16x2_hi(v2, v3, r2, r3);
        uint32_t l01 = bf16x2_of(r0, r1);
        uint32_t l23 = bf16x2_of(r2, r3);
        *reinterpret_cast<uint32_t*>(Ah + (row * ASTR + col0) * 2) = h01;
        *reinterpret_cast<uint32_t*>(Ah + ((row + 8) * ASTR + col0) * 2) = h23;
        *reinterpret_cast<uint32_t*>(Al + (row * ASTR + col0) * 2) = l01;
        *reinterpret_cast<uint32_t*>(Al + ((row + 8) * ASTR + col0) * 2) = l23;
    }
}

// ---------- single-sample dense layer (f32x2) ----------
template<int IN, int OUT, int OUTP, bool ACT>
__device__ __forceinline__ void dense1(const float* __restrict__ x, float* __restrict__ y,
                                       const float* __restrict__ W, const float* __restrict__ b) {
    constexpr int P = OUTP / 2;
    ull a[P];
#pragma unroll
    for (int j = 0; j < P; j++) a[j] = reinterpret_cast<const ull*>(b)[j];
#pragma unroll 4
    for (int i = 0; i < IN; i++) {
        ull xp = pack2(x[i]);
        const ulonglong2* Wr = reinterpret_cast<const ulonglong2*>(W + i * OUTP);
#pragma unroll
        for (int j = 0; j < P / 2; j++) {
            ulonglong2 w = Wr[j];
            a[2*j]   = fma2(xp, w.x, a[2*j]);
            a[2*j+1] = fma2(xp, w.y, a[2*j+1]);
        }
    }
#pragma unroll
    for (int j = 0; j < P; j++) { float lo, hi; unpack2(lo, hi, a[j]); y[2*j] = lo; y[2*j+1] = hi; }
    if (ACT) {
#pragma unroll
        for (int j = 0; j < OUT; j++) y[j] = tanh_fast(y[j]);
    }
}

// ---------- prep ----------
__device__ __forceinline__ void padcpy(int off, const float* __restrict__ src,
                                       int IN, int OUT, int OUTP, int gt, int gn) {
    for (int idx = gt; idx < IN * OUTP; idx += gn) {
        int i = idx / OUTP, j = idx - i * OUTP;
        g_wpad[off + idx] = (j < OUT) ? src[i * OUT + j] : 0.0f;
    }
}
__device__ __forceinline__ void padb(int off, const float* __restrict__ src,
                                     int OUT, int OUTP, int gt) {
    if (gt < OUTP) g_wpad[off + gt] = (gt < OUT) ? src[gt] : 0.0f;
}
__device__ __forceinline__ void wimg_fill(int offH, int offL, const float* __restrict__ src,
                                          int Np, int wstr, int Nreal, int Kreal, int srcN,
                                          int gt, int gn) {
    // W^T[n][k] = src[k*srcN + n], split hi/lo, zero-padded
    for (int idx = gt; idx < Np * wstr; idx += gn) {
        int n = idx / wstr, k = idx - n * wstr;
        float v = (n < Nreal && k < Kreal) ? src[k * srcN + n] : 0.0f;
        __nv_bfloat16 h = __float2bfloat16(v);
        __nv_bfloat16 l = __float2bfloat16(v - __bfloat162float(h));
        g_wimg[offH + idx] = *reinterpret_cast<unsigned short*>(&h);
        g_wimg[offL + idx] = *reinterpret_cast<unsigned short*>(&l);
    }
}

__global__ void prep(Params p) {
    int gt = blockIdx.x * blockDim.x + threadIdx.x;
    int gn = gridDim.x * blockDim.x;
    if (gt < 152) g_stats[gt] = 0.0f;
    padcpy(OW5,  p.w[4],   4, 10, 12, gt, gn);
    padcpy(OW6,  p.w[5],  10, 30, 32, gt, gn);
    padcpy(OW7,  p.w[6],  30, 60, 60, gt, gn);
    padcpy(OW10, p.w[9],  10, 10, 12, gt, gn);
    for (int idx = gt; idx < 720; idx += gn) {        // fused W89 = W8@W9
        int a = idx / 12, j = idx - a * 12;
        float s = 0.0f;
        if (j < 10) {
#pragma unroll 4
            for (int d = 0; d < 120; d++) s += p.w[7][a * 120 + d] * p.w[8][d * 10 + j];
        }
        g_wpad[OW89 + idx] = s;
    }
    if (gt >= 720 && gt < 732) {
        int j = gt - 720;
        float s = 0.0f;
        if (j < 10) {
            for (int d = 0; d < 120; d++) s += p.b[7][d] * p.w[8][d * 10 + j];
            s += p.b[8][j];
        }
        g_wpad[OB89 + j] = s;
    }
    padb(OB1,  p.b[0], 60, 60, gt);
    padb(OB2,  p.b[1], 30, 32, gt);
    padb(OB3,  p.b[2], 10, 12, gt);
    padb(OB4,  p.b[3],  4,  4, gt);
    padb(OB5,  p.b[4], 10, 12, gt);
    padb(OB6,  p.b[5], 30, 32, gt);
    padb(OB7,  p.b[6], 60, 60, gt);
    padb(OB10, p.b[9], 10, 12, gt);

    wimg_fill(WI_W1H, WI_W1L, p.w[0], 64, WSTR1, 60, 120,  60, gt, gn);
    wimg_fill(WI_W2H, WI_W2L, p.w[1], 32, WSTR2, 30,  60,  30, gt, gn);
    wimg_fill(WI_W3H, WI_W3L, p.w[2], 16, WSTR3, 10,  30,  10, gt, gn);
    wimg_fill(WI_W4H, WI_W4L, p.w[3],  8, WSTR4,  4,  10,   4, gt, gn);
}

__global__ void dummy_k() {}

// ---------- phase 1a: encoder L1..L4 on mma.sync + ldmatrix, writes zc ----------
__global__ __launch_bounds__(TPB, 2)
void phase1a(const float* __restrict__ x_in, float* __restrict__ zc_out,
             int N, int nChunks) {
    extern __shared__ __align__(16) char ap[];
    char* AhB = ap + SB_AH;
    char* AlB = ap + SB_AL;
    __shared__ float sb1[64], sb2[32], sb3[16], sb4[8];

    int tid = threadIdx.x;
    int w = tid >> 5, lane = tid & 31;
    int gid = lane >> 2, tig = lane & 3;
    int Rb0 = w * 16;
    int Rbase = Rb0 + gid;

    uint32_t AhU = smem_u32(AhB);
    uint32_t AlU = smem_u32(AlB);
    uint32_t WIu = smem_u32(ap + SB_WI);
    uint32_t W1H = WIu + WI_W1H * 2, W1L = WIu + WI_W1L * 2;
    uint32_t W2H = WIu + WI_W2H * 2, W2L = WIu + WI_W2L * 2;
    uint32_t W3H = WIu + WI_W3H * 2, W3L = WIu + WI_W3L * 2;
    uint32_t W4H = WIu + WI_W4H * 2, W4L = WIu + WI_W4L * 2;

    // stage W image (linear ull copy) + biases (bounds-checked, no gmem pad races)
    {
        const ull* src = reinterpret_cast<const ull*>(g_wimg);
        ull* dst = reinterpret_cast<ull*>(ap + SB_WI);
        for (int i = tid; i < WI_TOT / 4; i += TPB) dst[i] = src[i];
    }
    if (tid < 64) sb1[tid] = (tid < 60) ? g_wpad[OB1 + tid] : 0.0f;
    if (tid >= 64 && tid < 96)  sb2[tid - 64]  = (tid - 64 < 30) ? g_wpad[OB2 + tid - 64] : 0.0f;
    if (tid >= 96 && tid < 112) sb3[tid - 96]  = (tid - 96 < 10) ? g_wpad[OB3 + tid - 96] : 0.0f;
    if (tid >= 112 && tid < 120) sb4[tid - 112] = (tid - 112 < 4) ? g_wpad[OB4 + tid - 112] : 0.0f;

#pragma unroll 1
    for (int cid = blockIdx.x; cid < nChunks; cid += GRID1) {
        int base = cid * CHT;
        int rows = N - base; if (rows > CHT) rows = CHT;

        __syncthreads();   // W staged (iter0) / prior chunk frag reads done
        // ---- stage x hi/lo: 128 rows x 128 cols bf16 (zero-padded) ----
#pragma unroll 1
        for (int idx = tid; idx < 128 * 32; idx += TPB) {
            int r = idx >> 5, c = idx & 31;
            float4 v = make_float4(0.f, 0.f, 0.f, 0.f);
            if (r < rows && c < 30)
                v = *reinterpret_cast<const float4*>(x_in + (size_t)(base + r) * 120 + c * 4);
            float r0, r1, r2, r3;
            uint32_t h01 = bf16x2_hi(v.x, v.y, r0, r1);
            uint32_t h23 = bf16x2_hi(v.z, v.w, r2, r3);
            uint32_t l01 = bf16x2_of(r0, r1);
            uint32_t l23 = bf16x2_of(r2, r3);
            ull hv, lv;
            asm("mov.b64 %0, {%1,%2};" : "=l"(hv) : "r"(h01), "r"(h23));
            asm("mov.b64 %0, {%1,%2};" : "=l"(lv) : "r"(l01), "r"(l23));
            *reinterpret_cast<ull*>(AhB + (r * ASTR + c * 4) * 2) = hv;
            *reinterpret_cast<ull*>(AlB + (r * ASTR + c * 4) * 2) = lv;
        }
        __syncthreads();

        // ---- L1: 120->60 ----
        float d1[8][4];
        mma_stage<8, 8>(AhU, AlU, W1H, W1L, WSTR1, d1, Rb0, lane);
        __syncthreads();
        conv_store<8>(d1, sb1, AhB, AlB, Rbase, tig);
        __syncthreads();

        // ---- L2: 60->30 ----
        float d2[4][4];
        mma_stage<4, 4>(AhU, AlU, W2H, W2L, WSTR2, d2, Rb0, lane);
        __syncthreads();
        conv_store<4>(d2, sb2, AhB, AlB, Rbase, tig);
        __syncthreads();

        // ---- L3: 30->10 ----
        float d3[2][4];
        mma_stage<2, 2>(AhU, AlU, W3H, W3L, WSTR3, d3, Rb0, lane);
        __syncthreads();
        conv_store<2>(d3, sb3, AhB, AlB, Rbase, tig);
        __syncthreads();

        // ---- L4: 10->4 (no tanh) -> zc ----
        float d4[1][4];
        mma_stage<1, 1>(AhU, AlU, W4H, W4L, WSTR4, d4, Rb0, lane);
        if (tig < 2) {
            float bx = sb4[tig * 2], by = sb4[tig * 2 + 1];
            if (Rbase < rows)
                *reinterpret_cast<float2*>(zc_out + (size_t)(base + Rbase) * 4 + tig * 2) =
                    make_float2(d4[0][0] + bx, d4[0][1] + by);
            if (Rbase + 8 < rows)
                *reinterpret_cast<float2*>(zc_out + (size_t)(base + Rbase + 8) * 4 + tig * 2) =
                    make_float2(d4[0][2] + bx, d4[0][3] + by);
        }
    }
}

__device__ __forceinline__ void finish_softmax(const float* __restrict__ g,
                                               float* __restrict__ gamma_out, int n) {
    float m = g[0];
#pragma unroll
    for (int j = 1; j < 10; j++) m = fmaxf(m, g[j]);
    float e[10], s = 0.f;
#pragma unroll
    for (int j = 0; j < 10; j++) { e[j] = __expf(g[j] - m); s += e[j]; }
    float inv = __fdividef(1.0f, s);
    float2* gp = reinterpret_cast<float2*>(gamma_out + (size_t)n * 10);
#pragma unroll
    for (int t = 0; t < 5; t++) gp[t] = make_float2(e[2*t] * inv, e[2*t+1] * inv);
}

// ---------- phase 1b: decoder+estimation L5..L10 (scalar) ----------
__global__ __launch_bounds__(256, 2)
void phase1b(const float* __restrict__ zc_in, float* __restrict__ gamma_out, int N) {
    __shared__ float sWs[SC2_FLOATS];
    int tid = threadIdx.x;

    {
        const float4* src = reinterpret_cast<const float4*>(g_wpad + SBASE2);
        float4* dst = reinterpret_cast<float4*>(sWs);
        for (int i = tid; i < SC2_FLOATS / 4; i += 256) dst[i] = src[i];
    }
    __syncthreads();

    int n = blockIdx.x * 256 + tid;
    if (n >= N) return;

    float4 z4 = reinterpret_cast<const float4*>(zc_in)[n];
    float zc[4] = {z4.x, z4.y, z4.z, z4.w};

    float A[60], B[60];
    dense1<4,10,12,true>(zc, B, sWs + SOF2(OW5), sWs + SOF2(OB5));   // L5
    dense1<10,30,32,true>(B, A, sWs + SOF2(OW6), sWs + SOF2(OB6));   // L6
    dense1<30,60,60,true>(A, B, sWs + SOF2(OW7), sWs + SOF2(OB7));   // L7
    float z9[12];
    dense1<60,10,12,true>(B, z9, sWs + SOF2(OW89), sWs + SOF2(OB89)); // fused L8+L9
    float g[12];
    dense1<10,10,12,false>(z9, g, sWs + SOF2(OW10), sWs + SOF2(OB10));
    finish_softmax(g, gamma_out, n);
}

// ---------- phase 2: moment reduction (smem-staged atomics) ----------
__global__ __launch_bounds__(256, 1)
void phase2(const float* __restrict__ gamma, const float* __restrict__ zc, int N) {
    __shared__ float wsum[8][150];
    float acc[150];
#pragma unroll
    for (int v = 0; v < 150; v++) acc[v] = 0.0f;

    int stride = gridDim.x * blockDim.x;
    for (int n = blockIdx.x * blockDim.x + threadIdx.x; n < N; n += stride) {
        float g[10];
        const float2* gp = reinterpret_cast<const float2*>(gamma + (size_t)n * 10);
#pragma unroll
        for (int t = 0; t < 5; t++) { float2 v = gp[t]; g[2*t] = v.x; g[2*t+1] = v.y; }
        float4 z4 = reinterpret_cast<const float4*>(zc)[n];
        float zv[4] = {z4.x, z4.y, z4.z, z4.w};
        float zz[10];
        {
            int t = 0;
#pragma unroll
            for (int d = 0; d < 4; d++)
#pragma unroll
                for (int e = d; e < 4; e++) zz[t++] = zv[d] * zv[e];
        }
#pragma unroll
        for (int k = 0; k < 10; k++) {
            float gk = g[k];
            acc[k] += gk;
#pragma unroll
            for (int d = 0; d < 4; d++) acc[10 + k*4 + d] += gk * zv[d];
#pragma unroll
            for (int t = 0; t < 10; t++) acc[50 + k*10 + t] += gk * zz[t];
        }
    }
#pragma unroll
    for (int v = 0; v < 150; v++) {
        float x = acc[v];
        x += __shfl_xor_sync(0xffffffffu, x, 16);
        x += __shfl_xor_sync(0xffffffffu, x, 8);
        x += __shfl_xor_sync(0xffffffffu, x, 4);
        x += __shfl_xor_sync(0xffffffffu, x, 2);
        x += __shfl_xor_sync(0xffffffffu, x, 1);
        acc[v] = x;
    }
    int wid = threadIdx.x >> 5;
    if ((threadIdx.x & 31) == 0) {
#pragma unroll
        for (int v = 0; v < 150; v++) wsum[wid][v] = acc[v];
    }
    __syncthreads();
    if (threadIdx.x < 150) {
        float s = 0.f;
#pragma unroll
        for (int w = 0; w < 8; w++) s += wsum[w][threadIdx.x];
        atomicAdd(&g_stats[threadIdx.x], s);
    }
}

// ---------- phase 3+4 fused ----------
__global__ __launch_bounds__(256)
void phase34(const float* __restrict__ zc, float* __restrict__ energy,
             float* __restrict__ cov_out, float invN, int N) {
    __shared__ float sp[212];
    int k = threadIdx.x;
    if (k < 10) {
        float sg = g_stats[k];
        float isg = 1.0f / sg;
        float mu[4];
#pragma unroll
        for (int d = 0; d < 4; d++) mu[d] = g_stats[10 + 4*k + d] * isg;
        float C[4][4];
        {
            int t = 0;
#pragma unroll
            for (int d = 0; d < 4; d++)
#pragma unroll
                for (int e = d; e < 4; e++) {
                    float c = g_stats[50 + 10*k + t] * isg - mu[d] * mu[e];
                    C[d][e] = c; C[e][d] = c; t++;
                }
        }
        if (blockIdx.x == 0) {
#pragma unroll
            for (int d = 0; d < 4; d++)
#pragma unroll
                for (int e = 0; e < 4; e++) cov_out[k*16 + d*4 + e] = C[d][e];
        }
#pragma unroll
        for (int d = 0; d < 4; d++) C[d][d] += 1e-6f;

        float L00 = sqrtf(C[0][0]);
        float L10 = C[1][0] / L00, L20 = C[2][0] / L00, L30 = C[3][0] / L00;
        float L11 = sqrtf(C[1][1] - L10*L10);
        float L21 = (C[2][1] - L20*L10) / L11;
        float L31 = (C[3][1] - L30*L10) / L11;
        float L22 = sqrtf(C[2][2] - L20*L20 - L21*L21);
        float L32 = (C[3][2] - L30*L20 - L31*L21) / L22;
        float L33 = sqrtf(C[3][3] - L30*L30 - L31*L31 - L32*L32);
        float logdet = 2.0f * (logf(L00) + logf(L11) + logf(L22) + logf(L33));

        float M00 = 1.0f/L00, M11 = 1.0f/L11, M22 = 1.0f/L22, M33 = 1.0f/L33;
        float M10 = -L10 * M00 * M11;
        float M20 = -(L20*M00 + L21*M10) * M22;
        float M21 = -L21 * M11 * M22;
        float M30 = -(L30*M00 + L31*M10 + L32*M20) * M33;
        float M31 = -(L31*M11 + L32*M21) * M33;
        float M32 = -L32 * M22 * M33;

        float P[4][4];
        P[0][0] = M00*M00 + M10*M10 + M20*M20 + M30*M30;
        P[0][1] = M10*M11 + M20*M21 + M30*M31;
        P[0][2] = M20*M22 + M30*M32;
        P[0][3] = M30*M33;
        P[1][1] = M11*M11 + M21*M21 + M31*M31;
        P[1][2] = M21*M22 + M31*M32;
        P[1][3] = M31*M33;
        P[2][2] = M22*M22 + M32*M32;
        P[2][3] = M32*M33;
        P[3][3] = M33*M33;
        P[1][0] = P[0][1]; P[2][0] = P[0][2]; P[3][0] = P[0][3];
        P[2][1] = P[1][2]; P[3][1] = P[1][3]; P[3][2] = P[2][3];

        float phi = sg * invN;
        const float LOG2PI = 1.8378770664093453f;
        float ck = logf(phi) - 0.5f * (logdet + 4.0f * LOG2PI);

        float* o = sp + k * 21;
#pragma unroll
        for (int d = 0; d < 4; d++) o[d] = mu[d];
#pragma unroll
        for (int d = 0; d < 4; d++)
#pragma unroll
            for (int e = 0; e < 4; e++) o[4 + d*4 + e] = P[d][e];
        o[20] = ck;
    }
    __syncthreads();

    int n = blockIdx.x * blockDim.x + threadIdx.x;
    if (n >= N) return;
    float4 z = reinterpret_cast<const float4*>(zc)[n];
    float lp[10];
    float m = -1e30f;
#pragma unroll
    for (int kk = 0; kk < 10; kk++) {
        const float* o = sp + kk * 21;
        float d0 = z.x - o[0], d1 = z.y - o[1], d2 = z.z - o[2], d3 = z.w - o[3];
        const float* P = o + 4;
        float q = d0 * (P[0]*d0  + P[1]*d1  + P[2]*d2  + P[3]*d3)
                + d1 * (P[4]*d0  + P[5]*d1  + P[6]*d2  + P[7]*d3)
                + d2 * (P[8]*d0  + P[9]*d1  + P[10]*d2 + P[11]*d3)
                + d3 * (P[12]*d0 + P[13]*d1 + P[14]*d2 + P[15]*d3);
        lp[kk] = o[20] - 0.5f * q;
        m = fmaxf(m, lp[kk]);
    }
    float s = 0.f;
#pragma unroll
    for (int kk = 0; kk < 10; kk++) s += __expf(lp[kk] - m);
    energy[n] = -(m + __logf(s));
}

// ---------- launcher ----------
extern "C" void kernel_launch(void* const* d_in, const int* in_sizes, int n_in,
                              void* d_out, int out_size) {
    const float* x = (const float*)d_in[0];
    Params p;
    for (int i = 0; i < 10; i++) {
        p.w[i] = (const float*)d_in[1 + 2*i];
        p.b[i] = (const float*)d_in[2 + 2*i];
    }
    int N = in_sizes[0] / 120;
    int nChunks = (N + CHT - 1) / CHT;
    int nBlocks = (N + 255) / 256;

    float* out    = (float*)d_out;
    float* energy = out;                       // [N]
    float* gamma  = out + N;                   // [N,10]
    float* zcbuf  = out + (size_t)11 * N;      // [N,4]
    float* covbuf = out + (size_t)15 * N;      // [10,4,4]

    cudaFuncSetAttribute(phase1a, cudaFuncAttributeMaxDynamicSharedMemorySize, SMEM1A);

    prep<<<16, 256>>>(p);
    dummy_k<<<1, 32>>>();
    dummy_k<<<1, 32>>>();
    phase1a<<<GRID1, TPB, SMEM1A>>>(x, zcbuf, N, nChunks);   // profiler slot (index 3)
    phase1b<<<nBlocks, 256>>>(zcbuf, gamma, N);
    phase2<<<296, 256>>>(gamma, zcbuf, N);
    phase34<<<nBlocks, 256>>>(zcbuf, energy, covbuf, 1.0f / (float)N, N);
}

// round 16
// speedup vs baseline: 1.3386x; 1.3386x over previous
#include <cuda_runtime.h>
#include <cuda_bf16.h>
#include <math.h>
#include <stdint.h>

typedef unsigned long long ull;

#define TPB 256
#define GRID1 296      // phase1a: 2 CTAs/SM persistent
#define CHT 128        // samples per chunk (one M=128 MMA tile)
#define ASTR 132       // bf16 row stride for A tiles

// ---- gmem padded/fused scalar weight image (float offsets) ----
#define OW5  9520
#define OW6  9568
#define OW7  9888
#define OW89 11688
#define OW10 12408
#define OB1  12528
#define OB2  12588
#define OB3  12620
#define OB4  12632
#define OB5  12636
#define OB6  12648
#define OB7  12680
#define OB89 12740
#define OB10 12752
#define WTOTAL 12764
#define SBASE2 9520                    // phase1b copies [OW5, WTOTAL)
#define SOF2(x) ((x) - SBASE2)
#define SC2_FLOATS (WTOTAL - SBASE2)   // 3244

// ---- bf16 W image for MMA (bf16-element offsets), hi then lo per layer ----
#define WSTR1 132
#define WSTR2 72
#define WSTR3 40
#define WSTR4 24
#define WI_W1H 0        // 64 x 132
#define WI_W1L 8448
#define WI_W2H 16896    // 32 x 72
#define WI_W2L 19200
#define WI_W3H 21504    // 16 x 40
#define WI_W3L 22144
#define WI_W4H 22784    // 8 x 24
#define WI_W4L 22976
#define WI_TOT 23168    // 46,336 bytes

// ---- phase1a dynamic smem layout (bytes) ----
#define SB_AH  0                        // A hi: 128 x 132 bf16 = 33,792
#define SB_AL  33792
#define SB_WI  67584                    // W image block: 46,336
#define SMEM1A 113920                   // x2 = 227,840 -> 2 CTAs/SM

struct Params { const float* w[10]; const float* b[10]; };

__device__ float g_stats[152];
__device__ float g_wpad[WTOTAL];
__device__ unsigned short g_wimg[WI_TOT];

// ---------- math helpers ----------
__device__ __forceinline__ ull fma2(ull a, ull b, ull c) {
    ull d; asm("fma.rn.f32x2 %0, %1, %2, %3;" : "=l"(d) : "l"(a), "l"(b), "l"(c)); return d;
}
__device__ __forceinline__ ull pack2(float x) {
    ull r; asm("mov.b64 %0, {%1, %1};" : "=l"(r) : "f"(x)); return r;
}
__device__ __forceinline__ void unpack2(float& lo, float& hi, ull v) {
    asm("mov.b64 {%0, %1}, %2;" : "=f"(lo), "=f"(hi) : "l"(v));
}
__device__ __forceinline__ float tanh_fast(float x) {
    float e;
    asm("ex2.approx.f32 %0, %1;" : "=f"(e) : "f"(x * 2.8853900817779268f));
    float r;
    asm("rcp.approx.f32 %0, %1;" : "=f"(r) : "f"(e + 1.0f));
    return fmaf(-2.0f, r, 1.0f);
}
__device__ __forceinline__ void mma_bf16(float* d, const uint32_t* a, uint32_t b0, uint32_t b1) {
    asm volatile(
        "mma.sync.aligned.m16n8k16.row.col.f32.bf16.bf16.f32 "
        "{%0,%1,%2,%3}, {%4,%5,%6,%7}, {%8,%9}, {%0,%1,%2,%3};"
        : "+f"(d[0]), "+f"(d[1]), "+f"(d[2]), "+f"(d[3])
        : "r"(a[0]), "r"(a[1]), "r"(a[2]), "r"(a[3]), "r"(b0), "r"(b1));
}
__device__ __forceinline__ uint32_t bf16x2_hi(float a, float b, float& ra, float& rb) {
    __nv_bfloat162 h = __floats2bfloat162_rn(a, b);
    ra = a - __bfloat162float(h.x);
    rb = b - __bfloat162float(h.y);
    return *reinterpret_cast<uint32_t*>(&h);
}
__device__ __forceinline__ uint32_t bf16x2_of(float a, float b) {
    __nv_bfloat162 h = __floats2bfloat162_rn(a, b);
    return *reinterpret_cast<uint32_t*>(&h);
}

// ---------- MMA stage: d[NT][4] = A(128xK) @ W^T, split-bf16 3-product ----------
template<int NT, int KT>
__device__ __forceinline__ void mma_stage(const char* Ah, const char* Al,
                                          const unsigned short* Wh, const unsigned short* Wl,
                                          int wstr, float (&d)[NT][4],
                                          int Rbase, int gid, int tig) {
#pragma unroll
    for (int nt = 0; nt < NT; nt++)
#pragma unroll
        for (int q = 0; q < 4; q++) d[nt][q] = 0.0f;
#pragma unroll
    for (int kt = 0; kt < KT; kt++) {
        int cb = kt * 16 + tig * 2;
        uint32_t aH[4], aL[4];
        aH[0] = *reinterpret_cast<const uint32_t*>(Ah + (Rbase * ASTR + cb) * 2);
        aH[1] = *reinterpret_cast<const uint32_t*>(Ah + ((Rbase + 8) * ASTR + cb) * 2);
        aH[2] = *reinterpret_cast<const uint32_t*>(Ah + (Rbase * ASTR + cb + 8) * 2);
        aH[3] = *reinterpret_cast<const uint32_t*>(Ah + ((Rbase + 8) * ASTR + cb + 8) * 2);
        aL[0] = *reinterpret_cast<const uint32_t*>(Al + (Rbase * ASTR + cb) * 2);
        aL[1] = *reinterpret_cast<const uint32_t*>(Al + ((Rbase + 8) * ASTR + cb) * 2);
        aL[2] = *reinterpret_cast<const uint32_t*>(Al + (Rbase * ASTR + cb + 8) * 2);
        aL[3] = *reinterpret_cast<const uint32_t*>(Al + ((Rbase + 8) * ASTR + cb + 8) * 2);
#pragma unroll
        for (int nt = 0; nt < NT; nt++) {
            int nrow = nt * 8 + gid;
            uint32_t bH0 = *reinterpret_cast<const uint32_t*>(Wh + nrow * wstr + cb);
            uint32_t bH1 = *reinterpret_cast<const uint32_t*>(Wh + nrow * wstr + cb + 8);
            uint32_t bL0 = *reinterpret_cast<const uint32_t*>(Wl + nrow * wstr + cb);
            uint32_t bL1 = *reinterpret_cast<const uint32_t*>(Wl + nrow * wstr + cb + 8);
            mma_bf16(d[nt], aH, bH0, bH1);
            mma_bf16(d[nt], aL, bH0, bH1);
            mma_bf16(d[nt], aH, bL0, bL1);
        }
    }
}

// ---------- conversion: bias + tanh on frags -> split-bf16 A buffers ----------
template<int NT>
__device__ __forceinline__ void conv_store(float (&d)[NT][4], const float* __restrict__ bias,
                                           char* Ah, char* Al, int row, int tig) {
#pragma unroll
    for (int nt = 0; nt < NT; nt++) {
        int col0 = nt * 8 + tig * 2;
        float bx = bias[col0], by = bias[col0 + 1];
        float v0 = tanh_fast(d[nt][0] + bx);
        float v1 = tanh_fast(d[nt][1] + by);
        float v2 = tanh_fast(d[nt][2] + bx);
        float v3 = tanh_fast(d[nt][3] + by);
        float r0, r1, r2, r3;
        uint32_t h01 = bf16x2_hi(v0, v1, r0, r1);
        uint32_t h23 = bf16x2_hi(v2, v3, r2, r3);
        uint32_t l01 = bf16x2_of(r0, r1);
        uint32_t l23 = bf16x2_of(r2, r3);
        *reinterpret_cast<uint32_t*>(Ah + (row * ASTR + col0) * 2) = h01;
        *reinterpret_cast<uint32_t*>(Ah + ((row + 8) * ASTR + col0) * 2) = h23;
        *reinterpret_cast<uint32_t*>(Al + (row * ASTR + col0) * 2) = l01;
        *reinterpret_cast<uint32_t*>(Al + ((row + 8) * ASTR + col0) * 2) = l23;
    }
}

// ---------- single-sample dense layer (f32x2) ----------
template<int IN, int OUT, int OUTP, bool ACT>
__device__ __forceinline__ void dense1(const float* __restrict__ x, float* __restrict__ y,
                                       const float* __restrict__ W, const float* __restrict__ b) {
    constexpr int P = OUTP / 2;
    ull a[P];
#pragma unroll
    for (int j = 0; j < P; j++) a[j] = reinterpret_cast<const ull*>(b)[j];
#pragma unroll 4
    for (int i = 0; i < IN; i++) {
        ull xp = pack2(x[i]);
        const ulonglong2* Wr = reinterpret_cast<const ulonglong2*>(W + i * OUTP);
#pragma unroll
        for (int j = 0; j < P / 2; j++) {
            ulonglong2 w = Wr[j];
            a[2*j]   = fma2(xp, w.x, a[2*j]);
            a[2*j+1] = fma2(xp, w.y, a[2*j+1]);
        }
    }
#pragma unroll
    for (int j = 0; j < P; j++) { float lo, hi; unpack2(lo, hi, a[j]); y[2*j] = lo; y[2*j+1] = hi; }
    if (ACT) {
#pragma unroll
        for (int j = 0; j < OUT; j++) y[j] = tanh_fast(y[j]);
    }
}

// ---------- prep ----------
__device__ __forceinline__ void padcpy(int off, const float* __restrict__ src,
                                       int IN, int OUT, int OUTP, int gt, int gn) {
    for (int idx = gt; idx < IN * OUTP; idx += gn) {
        int i = idx / OUTP, j = idx - i * OUTP;
        g_wpad[off + idx] = (j < OUT) ? src[i * OUT + j] : 0.0f;
    }
}
__device__ __forceinline__ void padb(int off, const float* __restrict__ src,
                                     int OUT, int OUTP, int gt) {
    if (gt < OUTP) g_wpad[off + gt] = (gt < OUT) ? src[gt] : 0.0f;
}
__device__ __forceinline__ void wimg_fill(int offH, int offL, const float* __restrict__ src,
                                          int Np, int wstr, int Nreal, int Kreal, int srcN,
                                          int gt, int gn) {
    for (int idx = gt; idx < Np * wstr; idx += gn) {
        int n = idx / wstr, k = idx - n * wstr;
        float v = (n < Nreal && k < Kreal) ? src[k * srcN + n] : 0.0f;
        __nv_bfloat16 h = __float2bfloat16(v);
        __nv_bfloat16 l = __float2bfloat16(v - __bfloat162float(h));
        g_wimg[offH + idx] = *reinterpret_cast<unsigned short*>(&h);
        g_wimg[offL + idx] = *reinterpret_cast<unsigned short*>(&l);
    }
}

__global__ void prep(Params p) {
    int gt = blockIdx.x * blockDim.x + threadIdx.x;
    int gn = gridDim.x * blockDim.x;
    if (gt < 152) g_stats[gt] = 0.0f;
    padcpy(OW5,  p.w[4],   4, 10, 12, gt, gn);
    padcpy(OW6,  p.w[5],  10, 30, 32, gt, gn);
    padcpy(OW7,  p.w[6],  30, 60, 60, gt, gn);
    padcpy(OW10, p.w[9],  10, 10, 12, gt, gn);
    for (int idx = gt; idx < 720; idx += gn) {        // fused W89 = W8@W9
        int a = idx / 12, j = idx - a * 12;
        float s = 0.0f;
        if (j < 10) {
#pragma unroll 4
            for (int d = 0; d < 120; d++) s += p.w[7][a * 120 + d] * p.w[8][d * 10 + j];
        }
        g_wpad[OW89 + idx] = s;
    }
    if (gt >= 720 && gt < 732) {
        int j = gt - 720;
        float s = 0.0f;
        if (j < 10) {
            for (int d = 0; d < 120; d++) s += p.b[7][d] * p.w[8][d * 10 + j];
            s += p.b[8][j];
        }
        g_wpad[OB89 + j] = s;
    }
    padb(OB1,  p.b[0], 60, 60, gt);
    padb(OB2,  p.b[1], 30, 32, gt);
    padb(OB3,  p.b[2], 10, 12, gt);
    padb(OB4,  p.b[3],  4,  4, gt);
    padb(OB5,  p.b[4], 10, 12, gt);
    padb(OB6,  p.b[5], 30, 32, gt);
    padb(OB7,  p.b[6], 60, 60, gt);
    padb(OB10, p.b[9], 10, 12, gt);

    wimg_fill(WI_W1H, WI_W1L, p.w[0], 64, WSTR1, 60, 120,  60, gt, gn);
    wimg_fill(WI_W2H, WI_W2L, p.w[1], 32, WSTR2, 30,  60,  30, gt, gn);
    wimg_fill(WI_W3H, WI_W3L, p.w[2], 16, WSTR3, 10,  30,  10, gt, gn);
    wimg_fill(WI_W4H, WI_W4L, p.w[3],  8, WSTR4,  4,  10,   4, gt, gn);
}

__global__ void dummy_k() {}

// ---------- phase 1a: encoder L1..L4 on mma.sync, warp-scoped layer syncs ----------
__global__ __launch_bounds__(TPB, 2)
void phase1a(const float* __restrict__ x_in, float* __restrict__ zc_out,
             int N, int nChunks) {
    extern __shared__ __align__(16) char ap[];
    char* AhB = ap + SB_AH;
    char* AlB = ap + SB_AL;
    const unsigned short* WI = reinterpret_cast<const unsigned short*>(ap + SB_WI);
    __shared__ float sb1[64], sb2[32], sb3[16], sb4[8];

    int tid = threadIdx.x;
    int w = tid >> 5, lane = tid & 31;
    int gid = lane >> 2, tig = lane & 3;
    int Rbase = w * 16 + gid;

    // stage W image + biases (bounds-checked; no gmem pad races)
    {
        const ull* src = reinterpret_cast<const ull*>(g_wimg);
        ull* dst = reinterpret_cast<ull*>(ap + SB_WI);
        for (int i = tid; i < WI_TOT / 4; i += TPB) dst[i] = src[i];
    }
    if (tid < 64) sb1[tid] = (tid < 60) ? g_wpad[OB1 + tid] : 0.0f;
    if (tid >= 64 && tid < 96)  sb2[tid - 64]  = (tid - 64 < 30) ? g_wpad[OB2 + tid - 64] : 0.0f;
    if (tid >= 96 && tid < 112) sb3[tid - 96]  = (tid - 96 < 10) ? g_wpad[OB3 + tid - 96] : 0.0f;
    if (tid >= 112 && tid < 120) sb4[tid - 112] = (tid - 112 < 4) ? g_wpad[OB4 + tid - 112] : 0.0f;

#pragma unroll 1
    for (int cid = blockIdx.x; cid < nChunks; cid += GRID1) {
        int base = cid * CHT;
        int rows = N - base; if (rows > CHT) rows = CHT;

        __syncthreads();   // all warps done reading prior activations (block-wide staging next)
        // ---- stage x hi/lo: 128 rows x 128 cols bf16 (zero-padded) ----
#pragma unroll 1
        for (int idx = tid; idx < 128 * 32; idx += TPB) {
            int r = idx >> 5, c = idx & 31;
            float4 v = make_float4(0.f, 0.f, 0.f, 0.f);
            if (r < rows && c < 30)
                v = *reinterpret_cast<const float4*>(x_in + (size_t)(base + r) * 120 + c * 4);
            float r0, r1, r2, r3;
            uint32_t h01 = bf16x2_hi(v.x, v.y, r0, r1);
            uint32_t h23 = bf16x2_hi(v.z, v.w, r2, r3);
            uint32_t l01 = bf16x2_of(r0, r1);
            uint32_t l23 = bf16x2_of(r2, r3);
            ull hv, lv;
            asm("mov.b64 %0, {%1,%2};" : "=l"(hv) : "r"(h01), "r"(h23));
            asm("mov.b64 %0, {%1,%2};" : "=l"(lv) : "r"(l01), "r"(l23));
            *reinterpret_cast<ull*>(AhB + (r * ASTR + c * 4) * 2) = hv;
            *reinterpret_cast<ull*>(AlB + (r * ASTR + c * 4) * 2) = lv;
        }
        __syncthreads();

        // All subsequent smem activation traffic is warp-private (warp w owns
        // rows [w*16, w*16+16)) -> warp-scoped syncs suffice between layers.

        // ---- L1: 120->60 ----
        float d1[8][4];
        mma_stage<8, 8>(AhB, AlB, WI + WI_W1H, WI + WI_W1L, WSTR1, d1, Rbase, gid, tig);
        __syncwarp();
        conv_store<8>(d1, sb1, AhB, AlB, Rbase, tig);
        __syncwarp();

        // ---- L2: 60->30 ----
        float d2[4][4];
        mma_stage<4, 4>(AhB, AlB, WI + WI_W2H, WI + WI_W2L, WSTR2, d2, Rbase, gid, tig);
        __syncwarp();
        conv_store<4>(d2, sb2, AhB, AlB, Rbase, tig);
        __syncwarp();

        // ---- L3: 30->10 ----
        float d3[2][4];
        mma_stage<2, 2>(AhB, AlB, WI + WI_W3H, WI + WI_W3L, WSTR3, d3, Rbase, gid, tig);
        __syncwarp();
        conv_store<2>(d3, sb3, AhB, AlB, Rbase, tig);
        __syncwarp();

        // ---- L4: 10->4 (no tanh) -> zc ----
        float d4[1][4];
        mma_stage<1, 1>(AhB, AlB, WI + WI_W4H, WI + WI_W4L, WSTR4, d4, Rbase, gid, tig);
        if (tig < 2) {
            float bx = sb4[tig * 2], by = sb4[tig * 2 + 1];
            if (Rbase < rows)
                *reinterpret_cast<float2*>(zc_out + (size_t)(base + Rbase) * 4 + tig * 2) =
                    make_float2(d4[0][0] + bx, d4[0][1] + by);
            if (Rbase + 8 < rows)
                *reinterpret_cast<float2*>(zc_out + (size_t)(base + Rbase + 8) * 4 + tig * 2) =
                    make_float2(d4[0][2] + bx, d4[0][3] + by);
        }
    }
}

__device__ __forceinline__ void finish_softmax(const float* __restrict__ g,
                                               float* __restrict__ gamma_out, int n) {
    float m = g[0];
#pragma unroll
    for (int j = 1; j < 10; j++) m = fmaxf(m, g[j]);
    float e[10], s = 0.f;
#pragma unroll
    for (int j = 0; j < 10; j++) { e[j] = __expf(g[j] - m); s += e[j]; }
    float inv = __fdividef(1.0f, s);
    float2* gp = reinterpret_cast<float2*>(gamma_out + (size_t)n * 10);
#pragma unroll
    for (int t = 0; t < 5; t++) gp[t] = make_float2(e[2*t] * inv, e[2*t+1] * inv);
}

// ---------- phase 1b: decoder+estimation L5..L10 (scalar) ----------
__global__ __launch_bounds__(256, 2)
void phase1b(const float* __restrict__ zc_in, float* __restrict__ gamma_out, int N) {
    __shared__ float sWs[SC2_FLOATS];
    int tid = threadIdx.x;

    {
        const float4* src = reinterpret_cast<const float4*>(g_wpad + SBASE2);
        float4* dst = reinterpret_cast<float4*>(sWs);
        for (int i = tid; i < SC2_FLOATS / 4; i += 256) dst[i] = src[i];
    }
    __syncthreads();

    int n = blockIdx.x * 256 + tid;
    if (n >= N) return;

    float4 z4 = reinterpret_cast<const float4*>(zc_in)[n];
    float zc[4] = {z4.x, z4.y, z4.z, z4.w};

    float A[60], B[60];
    dense1<4,10,12,true>(zc, B, sWs + SOF2(OW5), sWs + SOF2(OB5));   // L5
    dense1<10,30,32,true>(B, A, sWs + SOF2(OW6), sWs + SOF2(OB6));   // L6
    dense1<30,60,60,true>(A, B, sWs + SOF2(OW7), sWs + SOF2(OB7));   // L7
    float z9[12];
    dense1<60,10,12,true>(B, z9, sWs + SOF2(OW89), sWs + SOF2(OB89)); // fused L8+L9
    float g[12];
    dense1<10,10,12,false>(z9, g, sWs + SOF2(OW10), sWs + SOF2(OB10));
    finish_softmax(g, gamma_out, n);
}

// ---------- phase 2: moment reduction (smem-staged atomics) ----------
__global__ __launch_bounds__(256, 1)
void phase2(const float* __restrict__ gamma, const float* __restrict__ zc, int N) {
    __shared__ float wsum[8][150];
    float acc[150];
#pragma unroll
    for (int v = 0; v < 150; v++) acc[v] = 0.0f;

    int stride = gridDim.x * blockDim.x;
    for (int n = blockIdx.x * blockDim.x + threadIdx.x; n < N; n += stride) {
        float g[10];
        const float2* gp = reinterpret_cast<const float2*>(gamma + (size_t)n * 10);
#pragma unroll
        for (int t = 0; t < 5; t++) { float2 v = gp[t]; g[2*t] = v.x; g[2*t+1] = v.y; }
        float4 z4 = reinterpret_cast<const float4*>(zc)[n];
        float zv[4] = {z4.x, z4.y, z4.z, z4.w};
        float zz[10];
        {
            int t = 0;
#pragma unroll
            for (int d = 0; d < 4; d++)
#pragma unroll
                for (int e = d; e < 4; e++) zz[t++] = zv[d] * zv[e];
        }
#pragma unroll
        for (int k = 0; k < 10; k++) {
            float gk = g[k];
            acc[k] += gk;
#pragma unroll
            for (int d = 0; d < 4; d++) acc[10 + k*4 + d] += gk * zv[d];
#pragma unroll
            for (int t = 0; t < 10; t++) acc[50 + k*10 + t] += gk * zz[t];
        }
    }
#pragma unroll
    for (int v = 0; v < 150; v++) {
        float x = acc[v];
        x += __shfl_xor_sync(0xffffffffu, x, 16);
        x += __shfl_xor_sync(0xffffffffu, x, 8);
        x += __shfl_xor_sync(0xffffffffu, x, 4);
        x += __shfl_xor_sync(0xffffffffu, x, 2);
        x += __shfl_xor_sync(0xffffffffu, x, 1);
        acc[v] = x;
    }
    int wid = threadIdx.x >> 5;
    if ((threadIdx.x & 31) == 0) {
#pragma unroll
        for (int v = 0; v < 150; v++) wsum[wid][v] = acc[v];
    }
    __syncthreads();
    if (threadIdx.x < 150) {
        float s = 0.f;
#pragma unroll
        for (int w = 0; w < 8; w++) s += wsum[w][threadIdx.x];
        atomicAdd(&g_stats[threadIdx.x], s);
    }
}

// ---------- phase 3+4 fused ----------
__global__ __launch_bounds__(256)
void phase34(const float* __restrict__ zc, float* __restrict__ energy,
             float* __restrict__ cov_out, float invN, int N) {
    __shared__ float sp[212];
    int k = threadIdx.x;
    if (k < 10) {
        float sg = g_stats[k];
        float isg = 1.0f / sg;
        float mu[4];
#pragma unroll
        for (int d = 0; d < 4; d++) mu[d] = g_stats[10 + 4*k + d] * isg;
        float C[4][4];
        {
            int t = 0;
#pragma unroll
            for (int d = 0; d < 4; d++)
#pragma unroll
                for (int e = d; e < 4; e++) {
                    float c = g_stats[50 + 10*k + t] * isg - mu[d] * mu[e];
                    C[d][e] = c; C[e][d] = c; t++;
                }
        }
        if (blockIdx.x == 0) {
#pragma unroll
            for (int d = 0; d < 4; d++)
#pragma unroll
                for (int e = 0; e < 4; e++) cov_out[k*16 + d*4 + e] = C[d][e];
        }
#pragma unroll
        for (int d = 0; d < 4; d++) C[d][d] += 1e-6f;

        float L00 = sqrtf(C[0][0]);
        float L10 = C[1][0] / L00, L20 = C[2][0] / L00, L30 = C[3][0] / L00;
        float L11 = sqrtf(C[1][1] - L10*L10);
        float L21 = (C[2][1] - L20*L10) / L11;
        float L31 = (C[3][1] - L30*L10) / L11;
        float L22 = sqrtf(C[2][2] - L20*L20 - L21*L21);
        float L32 = (C[3][2] - L30*L20 - L31*L21) / L22;
        float L33 = sqrtf(C[3][3] - L30*L30 - L31*L31 - L32*L32);
        float logdet = 2.0f * (logf(L00) + logf(L11) + logf(L22) + logf(L33));

        float M00 = 1.0f/L00, M11 = 1.0f/L11, M22 = 1.0f/L22, M33 = 1.0f/L33;
        float M10 = -L10 * M00 * M11;
        float M20 = -(L20*M00 + L21*M10) * M22;
        float M21 = -L21 * M11 * M22;
        float M30 = -(L30*M00 + L31*M10 + L32*M20) * M33;
        float M31 = -(L31*M11 + L32*M21) * M33;
        float M32 = -L32 * M22 * M33;

        float P[4][4];
        P[0][0] = M00*M00 + M10*M10 + M20*M20 + M30*M30;
        P[0][1] = M10*M11 + M20*M21 + M30*M31;
        P[0][2] = M20*M22 + M30*M32;
        P[0][3] = M30*M33;
        P[1][1] = M11*M11 + M21*M21 + M31*M31;
        P[1][2] = M21*M22 + M31*M32;
        P[1][3] = M31*M33;
        P[2][2] = M22*M22 + M32*M32;
        P[2][3] = M32*M33;
        P[3][3] = M33*M33;
        P[1][0] = P[0][1]; P[2][0] = P[0][2]; P[3][0] = P[0][3];
        P[2][1] = P[1][2]; P[3][1] = P[1][3]; P[3][2] = P[2][3];

        float phi = sg * invN;
        const float LOG2PI = 1.8378770664093453f;
        float ck = logf(phi) - 0.5f * (logdet + 4.0f * LOG2PI);

        float* o = sp + k * 21;
#pragma unroll
        for (int d = 0; d < 4; d++) o[d] = mu[d];
#pragma unroll
        for (int d = 0; d < 4; d++)
#pragma unroll
            for (int e = 0; e < 4; e++) o[4 + d*4 + e] = P[d][e];
        o[20] = ck;
    }
    __syncthreads();

    int n = blockIdx.x * blockDim.x + threadIdx.x;
    if (n >= N) return;
    float4 z = reinterpret_cast<const float4*>(zc)[n];
    float lp[10];
    float m = -1e30f;
#pragma unroll
    for (int kk = 0; kk < 10; kk++) {
        const float* o = sp + kk * 21;
        float d0 = z.x - o[0], d1 = z.y - o[1], d2 = z.z - o[2], d3 = z.w - o[3];
        const float* P = o + 4;
        float q = d0 * (P[0]*d0  + P[1]*d1  + P[2]*d2  + P[3]*d3)
                + d1 * (P[4]*d0  + P[5]*d1  + P[6]*d2  + P[7]*d3)
                + d2 * (P[8]*d0  + P[9]*d1  + P[10]*d2 + P[11]*d3)
                + d3 * (P[12]*d0 + P[13]*d1 + P[14]*d2 + P[15]*d3);
        lp[kk] = o[20] - 0.5f * q;
        m = fmaxf(m, lp[kk]);
    }
    float s = 0.f;
#pragma unroll
    for (int kk = 0; kk < 10; kk++) s += __expf(lp[kk] - m);
    energy[n] = -(m + __logf(s));
}

// ---------- launcher ----------
extern "C" void kernel_launch(void* const* d_in, const int* in_sizes, int n_in,
                              void* d_out, int out_size) {
    const float* x = (const float*)d_in[0];
    Params p;
    for (int i = 0; i < 10; i++) {
        p.w[i] = (const float*)d_in[1 + 2*i];
        p.b[i] = (const float*)d_in[2 + 2*i];
    }
    int N = in_sizes[0] / 120;
    int nChunks = (N + CHT - 1) / CHT;
    int nBlocks = (N + 255) / 256;

    float* out    = (float*)d_out;
    float* energy = out;                       // [N]
    float* gamma  = out + N;                   // [N,10]
    float* zcbuf  = out + (size_t)11 * N;      // [N,4]
    float* covbuf = out + (size_t)15 * N;      // [10,4,4]

    cudaFuncSetAttribute(phase1a, cudaFuncAttributeMaxDynamicSharedMemorySize, SMEM1A);

    prep<<<16, 256>>>(p);
    dummy_k<<<1, 32>>>();
    dummy_k<<<1, 32>>>();
    phase1a<<<GRID1, TPB, SMEM1A>>>(x, zcbuf, N, nChunks);   // profiler slot (index 3)
    phase1b<<<nBlocks, 256>>>(zcbuf, gamma, N);
    phase2<<<296, 256>>>(gamma, zcbuf, N);
    phase34<<<nBlocks, 256>>>(zcbuf, energy, covbuf, 1.0f / (float)N, N);
}